// round 14
// baseline (speedup 1.0000x reference)
#include <cuda_runtime.h>
#include <cuda_bf16.h>
#include <cuda_fp16.h>
#include <cstdint>
#include <math.h>

#define DM     512
#define BATCH  256
#define WIN    256
#define ENC    55
#define LATENT 128
#define BS     (BATCH * DM)

// ---------------- global scratch ----------------
__device__ float g_hs[BS];                        // fp32 h0 only (for hpr init)
__device__ __half g_hf16[(WIN + 1) * BS];         // fp16 hidden history (normal layout)
// h split ping-pong, K-CHUNKED swizzled layout:
// off(b,u) = (b>>6)<<15 | (u>>7)<<13 | (b&63)<<7 | ((((u>>3)&15) ^ (b&7))<<3) | (u&7)
__device__ __nv_bfloat16 g_hhi[2][BS];
__device__ __nv_bfloat16 g_hlo[2][BS];
__device__ __nv_bfloat16 g_whi[3 * DM * DM];      // W split hi (normal layout)
__device__ __nv_bfloat16 g_wlo[3 * DM * DM];      // W split lo
__device__ __half g_owhi[64 * DM];                // out_w fp16 split hi (rows padded to 64)
__device__ __half g_owlo[64 * DM];                // out_w fp16 split lo
__device__ unsigned g_bar4[4];                    // per-group arrival counters
__device__ volatile unsigned g_flag4[4];          // per-group release flags

// ---------------- PTX helpers ----------------
__device__ __forceinline__ uint32_t smem_u32(const void* p) {
    uint32_t a;
    asm("{ .reg .u64 t; cvta.to.shared.u64 t, %1; cvt.u32.u64 %0, t; }" : "=r"(a) : "l"(p));
    return a;
}
__device__ __forceinline__ void bulkcp(uint32_t dst, const void* src, uint32_t bytes,
                                       uint32_t mbar) {
    asm volatile("cp.async.bulk.shared::cluster.global.mbarrier::complete_tx::bytes "
                 "[%0], [%1], %2, [%3];"
                 :: "r"(dst), "l"(src), "r"(bytes), "r"(mbar) : "memory");
}
__device__ __forceinline__ void cp16(uint32_t dst, const void* src) {
    asm volatile("cp.async.cg.shared.global [%0], [%1], 16;" :: "r"(dst), "l"(src));
}
#define CP_COMMIT() asm volatile("cp.async.commit_group;" ::: "memory")
template <int N> __device__ __forceinline__ void cp_wait() {
    asm volatile("cp.async.wait_group %0;" :: "n"(N) : "memory");
}
#define MBAR_INIT(a, c) asm volatile("mbarrier.init.shared.b64 [%0], %1;" :: "r"(a), "r"(c) : "memory")
#define MBAR_EXPECT(a, bytes) \
    asm volatile("mbarrier.arrive.expect_tx.shared.b64 _, [%0], %1;" :: "r"(a), "r"(bytes) : "memory")
#define MBAR_WAIT(a, par) do {                                                              \
    uint32_t _m = (a), _p = (par), _d;                                                      \
    asm volatile("{ .reg .pred p; mbarrier.try_wait.parity.acquire.cta.shared::cta.b64 p, [%1], %2; selp.b32 %0,1,0,p; }" \
                 : "=r"(_d) : "r"(_m), "r"(_p) : "memory");                                 \
    if (!_d) {                                                                              \
        asm volatile("{ .reg .pred P1; WL%=: mbarrier.try_wait.parity.acquire.cta.shared::cta.b64 P1, [%0], %1, 0x989680; @P1 bra.uni WD%=; bra.uni WL%=; WD%=: }" \
                     :: "r"(_m), "r"(_p) : "memory");                                       \
    }                                                                                       \
} while (0)
#define FENCE_ASYNC()  asm volatile("fence.proxy.async;" ::: "memory")
#define FENCE_GPU()    asm volatile("fence.acq_rel.gpu;" ::: "memory")

__device__ __forceinline__ void ldsm_x4(uint32_t r[4], uint32_t addr) {
    asm volatile("ldmatrix.sync.aligned.m8n8.x4.shared.b16 {%0,%1,%2,%3}, [%4];"
                 : "=r"(r[0]), "=r"(r[1]), "=r"(r[2]), "=r"(r[3]) : "r"(addr));
}
__device__ __forceinline__ void ldsm_x2(uint32_t r[2], uint32_t addr) {
    asm volatile("ldmatrix.sync.aligned.m8n8.x2.shared.b16 {%0,%1}, [%2];"
                 : "=r"(r[0]), "=r"(r[1]) : "r"(addr));
}
__device__ __forceinline__ void mma_bf16(float c[4], const uint32_t a[4], const uint32_t b[2]) {
    asm volatile("mma.sync.aligned.m16n8k16.row.col.f32.bf16.bf16.f32 "
                 "{%0,%1,%2,%3}, {%4,%5,%6,%7}, {%8,%9}, {%0,%1,%2,%3};"
                 : "+f"(c[0]), "+f"(c[1]), "+f"(c[2]), "+f"(c[3])
                 : "r"(a[0]), "r"(a[1]), "r"(a[2]), "r"(a[3]), "r"(b[0]), "r"(b[1]));
}
__device__ __forceinline__ void mma_f16(float c[4], const uint32_t a[4], const uint32_t b[2]) {
    asm volatile("mma.sync.aligned.m16n8k16.row.col.f32.f16.f16.f32 "
                 "{%0,%1,%2,%3}, {%4,%5,%6,%7}, {%8,%9}, {%0,%1,%2,%3};"
                 : "+f"(c[0]), "+f"(c[1]), "+f"(c[2]), "+f"(c[3])
                 : "r"(a[0]), "r"(a[1]), "r"(a[2]), "r"(a[3]), "r"(b[0]), "r"(b[1]));
}
__device__ __forceinline__ float sigf(float x)  { return 1.f / (1.f + __expf(-x)); }
__device__ __forceinline__ float tanhf_fast(float x) {
    float e = __expf(2.f * x);
    return 1.f - 2.f / (e + 1.f);
}

// ---------------- persistent kernel config ----------------
#define NCTA    128
#define UT      16                    // units per CTA (N = 48)
#define MT      64                    // batch rows per CTA
#define GSZ     32                    // CTAs per batch group
// dyn smem layout (bytes):
#define WS_HI   0                     // 48 rows x 1024B, swizzled
#define WS_LO   49152
#define AS_BASE 98304                 // 4 K-chunks x (hi 16KB + lo 16KB)
#define AKCH_B  32768                 // per K-chunk bytes (hi+lo)
#define PART_OFF AS_BASE              // partial-sum exchange (reuses chunk0 post-sync)
#define DYN_BYTES 229376

// split-h elem offset (K-chunked swizzled tiles)
__device__ __forceinline__ int hsplit_off(int b, int u) {
    int r = b & 63;
    return ((b >> 6) << 15) + ((u >> 7) << 13) + (r << 7)
         + ((((u >> 3) & 15) ^ (r & 7)) << 3) + (u & 7);
}

__global__ void __launch_bounds__(256, 1)
gru_persistent(const float* __restrict__ b_ih, const float* __restrict__ b_hh) {
    extern __shared__ char dyn[];
    __shared__ __align__(16) uint64_t s_mbar[4];
    __shared__ float s_sr[UT], s_sz[UT], s_bin[UT], s_bhn[UT];

    const int tid = threadIdx.x;
    const int lane = tid & 31;
    const int warp = tid >> 5;
    const int wn = warp & 1;                // N half (24 cols)
    const int wm = (warp >> 1) & 1;         // M half (32 rows)
    const int kh = warp >> 2;               // K half (chunks 2kh, 2kh+1)
    const int cta = blockIdx.x;
    const int u0 = (cta & 31) * UT;
    const int grp = cta >> 5;               // batch group 0..3
    const int gb0 = grp * MT;
    const uint32_t sb = smem_u32(dyn);

    // ---- resident W tiles with gate-unit PERMUTED column order ----
    for (int idx = tid; idx < 48 * 64; idx += 256) {
        int n = idx >> 6, g = idx & 63;
        int nb = n / 24, rem = n % 24;
        int ni = rem >> 3, r2 = rem & 7;
        int q = r2 >> 1, e = r2 & 1;
        int j = ni * 2 + e;
        int usel = (j >= 3) ? 1 : 0;
        int gate = j - usel * 3;
        int gr = gate * DM + u0 + nb * 8 + q * 2 + usel;
        int sg = g ^ (n & 7);
        *reinterpret_cast<uint4*>(dyn + WS_HI + n * 1024 + sg * 16) =
            *reinterpret_cast<const uint4*>(g_whi + (size_t)gr * DM + g * 8);
        *reinterpret_cast<uint4*>(dyn + WS_LO + n * 1024 + sg * 16) =
            *reinterpret_cast<const uint4*>(g_wlo + (size_t)gr * DM + g * 8);
    }
    if (tid < UT) {
        int j = u0 + tid;
        s_sr[tid]  = b_ih[j] + b_hh[j];
        s_sz[tid]  = b_ih[DM + j] + b_hh[DM + j];
        s_bin[tid] = b_ih[2 * DM + j];
        s_bhn[tid] = b_hh[2 * DM + j];
    }
    if (tid == 0) {
        uint32_t mb = smem_u32(s_mbar);
#pragma unroll
        for (int i = 0; i < 4; i++) MBAR_INIT(mb + 8 * i, 1);
        FENCE_ASYNC();
    }
    __syncthreads();
    const uint32_t mb0 = smem_u32(s_mbar);

    // per-lane fragment addressing
    const int arowl = (lane & 7) + ((lane >> 3) & 1) * 8;     // row within 16-row frag
    const int aHalf = (lane >> 4) & 1;
    const int sA = arowl & 7;
    const uint32_t aBase = sb + AS_BASE + (uint32_t)(wm * 32 + arowl) * 256;
    const int sW = lane & 7;
    const int wHalf = (lane >> 3) & 1;
    const uint32_t wHiBase = sb + WS_HI + (uint32_t)(wn * 24 + (lane & 7)) * 1024;
    const uint32_t wLoBase = wHiBase + (WS_LO - WS_HI);

    // epilogue constants (each warp epilogues its own 16-row half: mt == kh)
    const int q = lane & 3;
    const int rlo = lane >> 2;
    const int ul0 = wn * 8 + q * 2;                 // local unit (even), +1 = odd
    const int erow = wm * 32 + kh * 16 + rlo;       // epilogue row base (local)
    // partial exchange slots: (pair p, writer kh) -> 1536B each
    char* const slot_w = dyn + PART_OFF + (((wm * 2 + wn) * 2 + kh) * 1536);
    const char* const slot_r = dyn + PART_OFF + (((wm * 2 + wn) * 2 + (kh ^ 1)) * 1536);

    // register-carried h_prev for this thread's fixed (batch, unit) pairs
    float2 hpr[2];
#pragma unroll
    for (int hh = 0; hh < 2; hh++) {
        const int b = gb0 + erow + hh * 8;
        hpr[hh] = *reinterpret_cast<const float2*>(&g_hs[(size_t)b * DM + u0 + ul0]);
    }

    for (int t = 0; t < WIN; t++) {
        // ---- issue K-chunked bulk copies (tid 0, proven form) ----
        if (tid == 0) {
            FENCE_ASYNC();
            const __nv_bfloat16* srcH = g_hhi[t & 1] + (grp << 15);
            const __nv_bfloat16* srcL = g_hlo[t & 1] + (grp << 15);
#pragma unroll
            for (int c = 0; c < 4; c++) MBAR_EXPECT(mb0 + 8 * c, AKCH_B);
#pragma unroll
            for (int c = 0; c < 4; c++) {
                bulkcp(sb + AS_BASE + c * AKCH_B, srcH + c * 8192, 16384, mb0 + 8 * c);
                bulkcp(sb + AS_BASE + c * AKCH_B + 16384, srcL + c * 8192, 16384, mb0 + 8 * c);
            }
        }

        float cf[2][3][4];
#pragma unroll
        for (int mt = 0; mt < 2; mt++)
#pragma unroll
            for (int ni = 0; ni < 3; ni++)
#pragma unroll
                for (int qq = 0; qq < 4; qq++) cf[mt][ni][qq] = 0.f;

        // ---- mainloop: this warp's K-half (2 chunks) ----
#pragma unroll
        for (int c2 = 0; c2 < 2; c2++) {
            const int kc = kh * 2 + c2;
            MBAR_WAIT(mb0 + 8 * kc, t & 1);
            const uint32_t aC = aBase + (uint32_t)kc * AKCH_B;
#pragma unroll
            for (int kk = 0; kk < 8; kk++) {
                const int cA = kk * 2 + aHalf;          // chunk-local A column
                const uint32_t a0 = aC + (uint32_t)((cA ^ sA) << 4);
                uint32_t ah0[4], ah1[4], al0[4], al1[4];
                ldsm_x4(ah0, a0);
                ldsm_x4(ah1, a0 + 4096);                // +16 rows
                ldsm_x4(al0, a0 + 16384);
                ldsm_x4(al1, a0 + 16384 + 4096);
                const int k16 = kc * 8 + kk;            // global k16 (for W)
                const int cW = k16 * 2 + wHalf;
                const uint32_t wOff = (uint32_t)((cW ^ sW) << 4);
                uint32_t bh[3][2], bl[3][2];
#pragma unroll
                for (int ni = 0; ni < 3; ni++) {
                    ldsm_x2(bh[ni], wHiBase + ni * 8192 + wOff);
                    ldsm_x2(bl[ni], wLoBase + ni * 8192 + wOff);
                }
#pragma unroll
                for (int ni = 0; ni < 3; ni++) {
                    mma_bf16(cf[0][ni], ah0, bh[ni]);
                    mma_bf16(cf[0][ni], ah0, bl[ni]);
                    mma_bf16(cf[0][ni], al0, bh[ni]);
                    mma_bf16(cf[1][ni], ah1, bh[ni]);
                    mma_bf16(cf[1][ni], ah1, bl[ni]);
                    mma_bf16(cf[1][ni], al1, bh[ni]);
                }
            }
        }

        __syncthreads();   // all A-chunk reads done; chunk0 region reusable

        // ---- K-split reduction: store partner-half partials ----
        {
            const int om = kh ^ 1;    // the half our partner epilogues
#pragma unroll
            for (int ni = 0; ni < 3; ni++)
                *reinterpret_cast<float4*>(slot_w + ni * 512 + lane * 16) =
                    make_float4(cf[om][ni][0], cf[om][ni][1], cf[om][ni][2], cf[om][ni][3]);
        }
        __syncthreads();

        // ---- sum partner partials + direct gate epilogue (own 16-row half) ----
        {
            float cfm[3][4];
#pragma unroll
            for (int ni = 0; ni < 3; ni++) {
                float4 v = *reinterpret_cast<const float4*>(slot_r + ni * 512 + lane * 16);
                cfm[ni][0] = cf[kh][ni][0] + v.x;
                cfm[ni][1] = cf[kh][ni][1] + v.y;
                cfm[ni][2] = cf[kh][ni][2] + v.z;
                cfm[ni][3] = cf[kh][ni][3] + v.w;
            }
            const float bsr0 = s_sr[ul0],      bsr1 = s_sr[ul0 + 1];
            const float bsz0 = s_sz[ul0],      bsz1 = s_sz[ul0 + 1];
            const float bin0 = s_bin[ul0],     bin1 = s_bin[ul0 + 1];
            const float bhn0 = s_bhn[ul0],     bhn1 = s_bhn[ul0 + 1];
#pragma unroll
            for (int hh = 0; hh < 2; hh++) {
                const int b = gb0 + erow + hh * 8;
                float gr0 = cfm[0][hh * 2 + 0], gz0 = cfm[0][hh * 2 + 1], gn0 = cfm[1][hh * 2 + 0];
                float gr1 = cfm[1][hh * 2 + 1], gz1 = cfm[2][hh * 2 + 0], gn1 = cfm[2][hh * 2 + 1];
                float r0v = sigf(bsr0 + gr0);
                float z0v = sigf(bsz0 + gz0);
                float n0v = tanhf_fast(bin0 + r0v * (bhn0 + gn0));
                float h0v = (1.f - z0v) * n0v + z0v * hpr[hh].x;
                float r1v = sigf(bsr1 + gr1);
                float z1v = sigf(bsz1 + gz1);
                float n1v = tanhf_fast(bin1 + r1v * (bhn1 + gn1));
                float h1v = (1.f - z1v) * n1v + z1v * hpr[hh].y;
                hpr[hh] = make_float2(h0v, h1v);
                // fp16 history (for output GEMM)
                *reinterpret_cast<__half2*>(
                    &g_hf16[(size_t)(t + 1) * BS + (size_t)b * DM + u0 + ul0]) =
                    __floats2half2_rn(h0v, h1v);
                // bf16 split ping-pong (for next-step MMA)
                __nv_bfloat16 hi0 = __float2bfloat16(h0v);
                __nv_bfloat16 hi1 = __float2bfloat16(h1v);
                __nv_bfloat16 lo0 = __float2bfloat16(h0v - __bfloat162float(hi0));
                __nv_bfloat16 lo1 = __float2bfloat16(h1v - __bfloat162float(hi1));
                int off = hsplit_off(b, u0 + ul0);
                __nv_bfloat162 vh; vh.x = hi0; vh.y = hi1;
                __nv_bfloat162 vl; vl.x = lo0; vl.y = lo1;
                *reinterpret_cast<__nv_bfloat162*>(&g_hhi[(t + 1) & 1][off]) = vh;
                *reinterpret_cast<__nv_bfloat162*>(&g_hlo[(t + 1) & 1][off]) = vl;
            }
        }
        __syncthreads();

        // ---- per-group grid barrier (release fence only) ----
        if (tid == 0) {
            FENCE_GPU();
            const unsigned tgt = (unsigned)(t + 1);
            unsigned old = atomicAdd(&g_bar4[grp], 1u);
            if (old == (unsigned)GSZ * tgt - 1u) {
                g_flag4[grp] = tgt;
            } else {
                while (g_flag4[grp] < tgt) { }
            }
        }
        __syncthreads();
    }
}

// ---------------- weight split prep ----------------
__global__ void prep_kernel(const float* __restrict__ w) {
    int i = blockIdx.x * blockDim.x + threadIdx.x;
    if (i < 3 * DM * DM) {
        float v = w[i];
        __nv_bfloat16 hi = __float2bfloat16(v);
        g_whi[i] = hi;
        g_wlo[i] = __float2bfloat16(v - __bfloat162float(hi));
    }
}

// out_w fp16 split prep (rows padded to 64 with zeros)
__global__ void prep_ow_kernel(const float* __restrict__ ow) {
    int i = blockIdx.x * blockDim.x + threadIdx.x;
    if (i < 64 * DM) {
        int r = i >> 9;
        float v = (r < ENC) ? ow[(size_t)r * DM + (i & 511)] : 0.f;
        __half hi = __float2half_rn(v);
        g_owhi[i] = hi;
        g_owlo[i] = __float2half_rn(v - __half2float(hi));
    }
}

// ---------------- h0 ----------------
__global__ void h0_kernel(const float* __restrict__ z,
                          const float* __restrict__ w,
                          const float* __restrict__ bias) {
    __shared__ float zs[LATENT];
    const int b = blockIdx.x;
    const int j = threadIdx.x;
    if (b == 0 && j < 4) { g_bar4[j] = 0; g_flag4[j] = 0; }   // reset per replay
    if (threadIdx.x < LATENT) zs[threadIdx.x] = z[b * LATENT + threadIdx.x];
    __syncthreads();
    float acc = 0.f;
    const float4* wr = reinterpret_cast<const float4*>(w + (size_t)j * LATENT);
#pragma unroll
    for (int k4 = 0; k4 < LATENT / 4; k4++) {
        float4 w4 = __ldg(&wr[k4]);
        acc += zs[4 * k4 + 0] * w4.x + zs[4 * k4 + 1] * w4.y
             + zs[4 * k4 + 2] * w4.z + zs[4 * k4 + 3] * w4.w;
    }
    float h = tanhf(acc + bias[j]);
    g_hs[(size_t)b * DM + j] = h;
    __nv_bfloat16 hi = __float2bfloat16(h);
    int off = hsplit_off(b, j);
    g_hhi[0][off] = hi;
    g_hlo[0][off] = __float2bfloat16(h - __bfloat162float(hi));
}

// ---------------- output GEMM: tensor cores, fp16 H x fp16-split W ----------------
#define OH_OFF 0
#define OW_OFF 32768
#define ODYN   65536
__global__ void __launch_bounds__(256)
out_kernel(const float* __restrict__ out_b, float* __restrict__ out) {
    extern __shared__ char odyn[];
    const int R0  = blockIdx.x * 128;
    const int tid = threadIdx.x;
    const int lane = tid & 31;
    const int warp = tid >> 5;
    const int wm = warp >> 1;
    const int wn = warp & 1;
    const uint32_t sb = smem_u32(odyn);
    const __half* __restrict__ hsrc = g_hf16 + (size_t)BS;

    float cf[2][4][4] = {};

    const int arowl = (lane & 7) + ((lane >> 3) & 1) * 8;
    const int aHalf = (lane >> 4) & 1;
    const int sA = arowl & 7;
    const int wrow = (lane & 7);
    const int sW = wrow;
    const int wHalf = (lane >> 3) & 1;

    for (int kc = 0; kc < 4; kc++) {
#pragma unroll
        for (int p = 0; p < 8; p++) {
            int idx = tid + 256 * p;
            int row = idx >> 4, c = idx & 15;
            cp16(sb + OH_OFF + row * 256 + ((c ^ (row & 7)) << 4),
                 hsrc + (size_t)(R0 + row) * DM + kc * 128 + c * 8);
        }
#pragma unroll
        for (int p = 0; p < 4; p++) {
            int idx = tid + 256 * p;
            int row = idx >> 4, c = idx & 15;
            cp16(sb + OW_OFF + row * 256 + ((c ^ (row & 7)) << 4),
                 g_owhi + (size_t)row * DM + kc * 128 + c * 8);
        }
#pragma unroll
        for (int p = 0; p < 4; p++) {
            int idx = tid + 256 * p;
            int row = idx >> 4, c = idx & 15;
            cp16(sb + OW_OFF + 16384 + row * 256 + ((c ^ (row & 7)) << 4),
                 g_owlo + (size_t)row * DM + kc * 128 + c * 8);
        }
        CP_COMMIT();
        cp_wait<0>();
        __syncthreads();

        const uint32_t aB = sb + OH_OFF + (uint32_t)(wm * 32 + arowl) * 256;
        const uint32_t wB = sb + OW_OFF + (uint32_t)(wn * 32 + wrow) * 256;
#pragma unroll
        for (int kk = 0; kk < 8; kk++) {
            const int cA = kk * 2 + aHalf;
            uint32_t ah0[4], ah1[4];
            ldsm_x4(ah0, aB + (uint32_t)((cA ^ sA) << 4));
            ldsm_x4(ah1, aB + 16 * 256 + (uint32_t)((cA ^ sA) << 4));
            const int cW = kk * 2 + wHalf;
            const uint32_t wOff = (uint32_t)((cW ^ sW) << 4);
            uint32_t bh[4][2], bl[4][2];
#pragma unroll
            for (int nt = 0; nt < 4; nt++) {
                ldsm_x2(bh[nt], wB + nt * 8 * 256 + wOff);
                ldsm_x2(bl[nt], wB + nt * 8 * 256 + 16384 + wOff);
            }
#pragma unroll
            for (int nt = 0; nt < 4; nt++) {
                mma_f16(cf[0][nt], ah0, bh[nt]);
                mma_f16(cf[0][nt], ah0, bl[nt]);
                mma_f16(cf[1][nt], ah1, bh[nt]);
                mma_f16(cf[1][nt], ah1, bl[nt]);
            }
        }
        __syncthreads();
    }

    const int c_lo = (lane & 3) * 2;
    const int r_in = lane >> 2;
#pragma unroll
    for (int mt = 0; mt < 2; mt++) {
#pragma unroll
        for (int nt = 0; nt < 4; nt++) {
            int col = wn * 32 + nt * 8 + c_lo;
            if (col >= ENC) continue;
            float b0 = __ldg(&out_b[col]);
            bool ok1 = (col + 1) < ENC;
            float b1 = ok1 ? __ldg(&out_b[col + 1]) : 0.f;
#pragma unroll
            for (int hh = 0; hh < 2; hh++) {
                int R = R0 + wm * 32 + mt * 16 + r_in + hh * 8;
                int tt = R >> 8, b = R & 255;
                float* o = &out[((size_t)b * WIN + tt) * ENC + col];
                o[0] = cf[mt][nt][hh * 2 + 0] + b0;
                if (ok1) o[1] = cf[mt][nt][hh * 2 + 1] + b1;
            }
        }
    }
}

// ---------------- launch ----------------
extern "C" void kernel_launch(void* const* d_in, const int* in_sizes, int n_in,
                              void* d_out, int out_size) {
    (void)in_sizes; (void)n_in; (void)out_size;
    const float* z        = (const float*)d_in[0];
    const float* h_proj_w = (const float*)d_in[1];
    const float* h_proj_b = (const float*)d_in[2];
    const float* w_hh     = (const float*)d_in[4];
    const float* b_ih     = (const float*)d_in[5];
    const float* b_hh     = (const float*)d_in[6];
    const float* out_w    = (const float*)d_in[7];
    const float* out_b    = (const float*)d_in[8];
    float* out = (float*)d_out;

    static bool attr_done = false;
    if (!attr_done) {
        cudaFuncSetAttribute(gru_persistent,
                             cudaFuncAttributeMaxDynamicSharedMemorySize, DYN_BYTES);
        cudaFuncSetAttribute(out_kernel,
                             cudaFuncAttributeMaxDynamicSharedMemorySize, ODYN);
        attr_done = true;
    }

    prep_kernel<<<(3 * DM * DM + 255) / 256, 256>>>(w_hh);
    prep_ow_kernel<<<(64 * DM + 255) / 256, 256>>>(out_w);
    h0_kernel<<<BATCH, DM>>>(z, h_proj_w, h_proj_b);
    gru_persistent<<<NCTA, 256, DYN_BYTES>>>(b_ih, b_hh);
    out_kernel<<<(WIN * BATCH) / 128, 256, ODYN>>>(out_b, out);
}

// round 15
// speedup vs baseline: 1.0474x; 1.0474x over previous
#include <cuda_runtime.h>
#include <cuda_bf16.h>
#include <cuda_fp16.h>
#include <cstdint>
#include <math.h>

#define DM     512
#define BATCH  256
#define WIN    256
#define ENC    55
#define LATENT 128
#define BS     (BATCH * DM)

// ---------------- global scratch ----------------
__device__ float g_hs[BS];                        // fp32 h0 only (for hpr init)
__device__ __half g_hf16[(WIN + 1) * BS];         // fp16 hidden history (normal layout)
// h split ping-pong, MERGED K-chunked swizzled layout:
// hi at hoff(b,u), lo at hoff(b,u)+8192 within the same 16K-elem chunk block
__device__ __nv_bfloat16 g_hsp[2][2 * BS];
__device__ __nv_bfloat16 g_whi[3 * DM * DM];      // W split hi (normal layout)
__device__ __nv_bfloat16 g_wlo[3 * DM * DM];      // W split lo
__device__ __half g_owhi[64 * DM];                // out_w fp16 split hi (rows padded to 64)
__device__ __half g_owlo[64 * DM];                // out_w fp16 split lo
__device__ unsigned g_wbar[128];                  // per-group warp-arrival counters (128B stride)

// ---------------- PTX helpers ----------------
__device__ __forceinline__ uint32_t smem_u32(const void* p) {
    uint32_t a;
    asm("{ .reg .u64 t; cvta.to.shared.u64 t, %1; cvt.u32.u64 %0, t; }" : "=r"(a) : "l"(p));
    return a;
}
__device__ __forceinline__ void bulkcp(uint32_t dst, const void* src, uint32_t bytes,
                                       uint32_t mbar) {
    asm volatile("cp.async.bulk.shared::cluster.global.mbarrier::complete_tx::bytes "
                 "[%0], [%1], %2, [%3];"
                 :: "r"(dst), "l"(src), "r"(bytes), "r"(mbar) : "memory");
}
__device__ __forceinline__ void cp16(uint32_t dst, const void* src) {
    asm volatile("cp.async.cg.shared.global [%0], [%1], 16;" :: "r"(dst), "l"(src));
}
#define CP_COMMIT() asm volatile("cp.async.commit_group;" ::: "memory")
template <int N> __device__ __forceinline__ void cp_wait() {
    asm volatile("cp.async.wait_group %0;" :: "n"(N) : "memory");
}
#define MBAR_INIT(a, c) asm volatile("mbarrier.init.shared.b64 [%0], %1;" :: "r"(a), "r"(c) : "memory")
#define MBAR_EXPECT(a, bytes) \
    asm volatile("mbarrier.arrive.expect_tx.shared.b64 _, [%0], %1;" :: "r"(a), "r"(bytes) : "memory")
#define MBAR_WAIT(a, par) do {                                                              \
    uint32_t _m = (a), _p = (par), _d;                                                      \
    asm volatile("{ .reg .pred p; mbarrier.try_wait.parity.acquire.cta.shared::cta.b64 p, [%1], %2; selp.b32 %0,1,0,p; }" \
                 : "=r"(_d) : "r"(_m), "r"(_p) : "memory");                                 \
    if (!_d) {                                                                              \
        asm volatile("{ .reg .pred P1; WL%=: mbarrier.try_wait.parity.acquire.cta.shared::cta.b64 P1, [%0], %1, 0x989680; @P1 bra.uni WD%=; bra.uni WL%=; WD%=: }" \
                     :: "r"(_m), "r"(_p) : "memory");                                       \
    }                                                                                       \
} while (0)
#define FENCE_ASYNC()  asm volatile("fence.proxy.async;" ::: "memory")
#define FENCE_GPU()    asm volatile("fence.acq_rel.gpu;" ::: "memory")

__device__ __forceinline__ unsigned ld_acq(const unsigned* p) {
    unsigned v;
    asm volatile("ld.global.acquire.gpu.b32 %0, [%1];" : "=r"(v) : "l"(p) : "memory");
    return v;
}
__device__ __forceinline__ void ldsm_x4(uint32_t r[4], uint32_t addr) {
    asm volatile("ldmatrix.sync.aligned.m8n8.x4.shared.b16 {%0,%1,%2,%3}, [%4];"
                 : "=r"(r[0]), "=r"(r[1]), "=r"(r[2]), "=r"(r[3]) : "r"(addr));
}
__device__ __forceinline__ void ldsm_x2(uint32_t r[2], uint32_t addr) {
    asm volatile("ldmatrix.sync.aligned.m8n8.x2.shared.b16 {%0,%1}, [%2];"
                 : "=r"(r[0]), "=r"(r[1]) : "r"(addr));
}
__device__ __forceinline__ void mma_bf16(float c[4], const uint32_t a[4], const uint32_t b[2]) {
    asm volatile("mma.sync.aligned.m16n8k16.row.col.f32.bf16.bf16.f32 "
                 "{%0,%1,%2,%3}, {%4,%5,%6,%7}, {%8,%9}, {%0,%1,%2,%3};"
                 : "+f"(c[0]), "+f"(c[1]), "+f"(c[2]), "+f"(c[3])
                 : "r"(a[0]), "r"(a[1]), "r"(a[2]), "r"(a[3]), "r"(b[0]), "r"(b[1]));
}
__device__ __forceinline__ void mma_f16(float c[4], const uint32_t a[4], const uint32_t b[2]) {
    asm volatile("mma.sync.aligned.m16n8k16.row.col.f32.f16.f16.f32 "
                 "{%0,%1,%2,%3}, {%4,%5,%6,%7}, {%8,%9}, {%0,%1,%2,%3};"
                 : "+f"(c[0]), "+f"(c[1]), "+f"(c[2]), "+f"(c[3])
                 : "r"(a[0]), "r"(a[1]), "r"(a[2]), "r"(a[3]), "r"(b[0]), "r"(b[1]));
}
__device__ __forceinline__ float sigf(float x)  { return 1.f / (1.f + __expf(-x)); }
__device__ __forceinline__ float tanhf_fast(float x) {
    float e = __expf(2.f * x);
    return 1.f - 2.f / (e + 1.f);
}

// ---------------- persistent kernel config ----------------
#define NCTA    128
#define UT      16                    // units per CTA (N = 48)
#define MT      64                    // batch rows per CTA
#define GSZ     32                    // CTAs per batch group
#define GW      (GSZ * 8)             // warp arrivals per group per step
// dyn smem layout (bytes):
#define WS_HI   0                     // 48 rows x 1024B, swizzled
#define WS_LO   49152
#define AS_BASE 98304                 // 4 K-chunks x (hi 16KB + lo 16KB)
#define AKCH_B  32768                 // per K-chunk bytes (hi+lo)
#define DYN_BYTES 229376

// merged split-h elem offset (hi plane; lo = +8192)
__device__ __forceinline__ int hoff(int b, int u) {
    int r = b & 63;
    return ((b >> 6) << 16) + (((u >> 7) & 3) << 14) + (r << 7)
         + ((((u >> 3) & 15) ^ (r & 7)) << 3) + (u & 7);
}

__global__ void __launch_bounds__(256, 1)
gru_persistent(const float* __restrict__ b_ih, const float* __restrict__ b_hh) {
    extern __shared__ char dyn[];
    __shared__ __align__(16) uint64_t s_mbar[4];
    __shared__ float s_sr[UT], s_sz[UT], s_bin[UT], s_bhn[UT];

    const int tid = threadIdx.x;
    const int lane = tid & 31;
    const int warp = tid >> 5;
    const int m_base = (warp >> 1) * 16;    // 4 M-tiles of 16 rows
    const int warp_n = warp & 1;
    const int n_base = warp_n * 24;
    const int cta = blockIdx.x;
    const int u0 = (cta & 31) * UT;
    const int grp = cta >> 5;               // batch group 0..3
    const int gb0 = grp * MT;
    const uint32_t sb = smem_u32(dyn);
    unsigned* const wbar = &g_wbar[grp << 5];

    // ---- resident W tiles with gate-unit PERMUTED column order ----
    for (int idx = tid; idx < 48 * 64; idx += 256) {
        int n = idx >> 6, g = idx & 63;
        int nb = n / 24, rem = n % 24;
        int ni = rem >> 3, r2 = rem & 7;
        int q = r2 >> 1, e = r2 & 1;
        int j = ni * 2 + e;
        int usel = (j >= 3) ? 1 : 0;
        int gate = j - usel * 3;
        int gr = gate * DM + u0 + nb * 8 + q * 2 + usel;
        int sg = g ^ (n & 7);
        *reinterpret_cast<uint4*>(dyn + WS_HI + n * 1024 + sg * 16) =
            *reinterpret_cast<const uint4*>(g_whi + (size_t)gr * DM + g * 8);
        *reinterpret_cast<uint4*>(dyn + WS_LO + n * 1024 + sg * 16) =
            *reinterpret_cast<const uint4*>(g_wlo + (size_t)gr * DM + g * 8);
    }
    if (tid < UT) {
        int j = u0 + tid;
        s_sr[tid]  = b_ih[j] + b_hh[j];
        s_sz[tid]  = b_ih[DM + j] + b_hh[DM + j];
        s_bin[tid] = b_ih[2 * DM + j];
        s_bhn[tid] = b_hh[2 * DM + j];
    }
    if (tid == 0) {
        uint32_t mb = smem_u32(s_mbar);
#pragma unroll
        for (int i = 0; i < 4; i++) MBAR_INIT(mb + 8 * i, 1);
        FENCE_ASYNC();
    }
    __syncthreads();
    const uint32_t mb0 = smem_u32(s_mbar);

    // per-lane fragment addressing
    const int arowl = (lane & 7) + ((lane >> 3) & 1) * 8;     // row within m-tile
    const int aHalf = (lane >> 4) & 1;
    const int sA = arowl & 7;
    const uint32_t aBase = sb + AS_BASE + (uint32_t)(m_base + arowl) * 256;
    const int sW = lane & 7;
    const int wHalf = (lane >> 3) & 1;
    const uint32_t wHiBase = sb + WS_HI + (uint32_t)(n_base + (lane & 7)) * 1024;
    const uint32_t wLoBase = wHiBase + (WS_LO - WS_HI);

    // epilogue constants
    const int q = lane & 3;
    const int rlo = lane >> 2;
    const int ul0 = warp_n * 8 + q * 2;     // local unit (even), +1 = odd

    // register-carried h_prev for this thread's fixed (batch, unit) pairs
    float2 hpr[2];
#pragma unroll
    for (int hh = 0; hh < 2; hh++) {
        const int b = gb0 + m_base + rlo + hh * 8;
        hpr[hh] = *reinterpret_cast<const float2*>(&g_hs[(size_t)b * DM + u0 + ul0]);
    }

    for (int t = 0; t < WIN; t++) {
        // ---- producer wait (group warp counter) + K-chunked bulk copies ----
        if (tid == 0) {
            if (t > 0) {
                const unsigned need = (unsigned)GW * (unsigned)t;
                while (ld_acq(wbar) < need) { }
            }
            FENCE_ASYNC();
            const __nv_bfloat16* src = g_hsp[t & 1] + (grp << 16);
#pragma unroll
            for (int c = 0; c < 4; c++) MBAR_EXPECT(mb0 + 8 * c, AKCH_B);
#pragma unroll
            for (int c = 0; c < 4; c++)
                bulkcp(sb + AS_BASE + c * AKCH_B, src + (c << 14), AKCH_B, mb0 + 8 * c);
        }

        float cf[3][4];
#pragma unroll
        for (int ni = 0; ni < 3; ni++)
#pragma unroll
            for (int qq = 0; qq < 4; qq++) cf[ni][qq] = 0.f;

#pragma unroll
        for (int kc = 0; kc < 4; kc++) {
            MBAR_WAIT(mb0 + 8 * kc, t & 1);
            const uint32_t aC = aBase + (uint32_t)kc * AKCH_B;
#pragma unroll
            for (int kk = 0; kk < 8; kk++) {
                const int cA = kk * 2 + aHalf;          // chunk-local A column
                const uint32_t aAddr = aC + (uint32_t)((cA ^ sA) << 4);
                uint32_t ah[4], al[4];
                ldsm_x4(ah, aAddr);
                ldsm_x4(al, aAddr + 16384);
                const int k16 = kc * 8 + kk;            // global k16 (for W)
                const int cW = k16 * 2 + wHalf;
                const uint32_t wOff = (uint32_t)((cW ^ sW) << 4);
                uint32_t bh[3][2], bl[3][2];
#pragma unroll
                for (int ni = 0; ni < 3; ni++) {
                    ldsm_x2(bh[ni], wHiBase + ni * 8192 + wOff);
                    ldsm_x2(bl[ni], wLoBase + ni * 8192 + wOff);
                }
#pragma unroll
                for (int ni = 0; ni < 3; ni++) {
                    mma_bf16(cf[ni], ah, bh[ni]);
                    mma_bf16(cf[ni], ah, bl[ni]);
                    mma_bf16(cf[ni], al, bh[ni]);
                }
            }
        }

        // ---- direct epilogue on fragments (h_prev in registers) ----
        {
            const float bsr0 = s_sr[ul0],      bsr1 = s_sr[ul0 + 1];
            const float bsz0 = s_sz[ul0],      bsz1 = s_sz[ul0 + 1];
            const float bin0 = s_bin[ul0],     bin1 = s_bin[ul0 + 1];
            const float bhn0 = s_bhn[ul0],     bhn1 = s_bhn[ul0 + 1];
            __nv_bfloat16* const hsp = g_hsp[(t + 1) & 1];
#pragma unroll
            for (int hh = 0; hh < 2; hh++) {
                const int b = gb0 + m_base + rlo + hh * 8;
                float gr0 = cf[0][hh * 2 + 0], gz0 = cf[0][hh * 2 + 1], gn0 = cf[1][hh * 2 + 0];
                float gr1 = cf[1][hh * 2 + 1], gz1 = cf[2][hh * 2 + 0], gn1 = cf[2][hh * 2 + 1];
                float r0v = sigf(bsr0 + gr0);
                float z0v = sigf(bsz0 + gz0);
                float n0v = tanhf_fast(bin0 + r0v * (bhn0 + gn0));
                float h0v = (1.f - z0v) * n0v + z0v * hpr[hh].x;
                float r1v = sigf(bsr1 + gr1);
                float z1v = sigf(bsz1 + gz1);
                float n1v = tanhf_fast(bin1 + r1v * (bhn1 + gn1));
                float h1v = (1.f - z1v) * n1v + z1v * hpr[hh].y;
                hpr[hh] = make_float2(h0v, h1v);
                // fp16 history (for output GEMM)
                *reinterpret_cast<__half2*>(
                    &g_hf16[(size_t)(t + 1) * BS + (size_t)b * DM + u0 + ul0]) =
                    __floats2half2_rn(h0v, h1v);
                // merged bf16 split ping-pong (for next-step MMA)
                __nv_bfloat16 hi0 = __float2bfloat16(h0v);
                __nv_bfloat16 hi1 = __float2bfloat16(h1v);
                __nv_bfloat16 lo0 = __float2bfloat16(h0v - __bfloat162float(hi0));
                __nv_bfloat16 lo1 = __float2bfloat16(h1v - __bfloat162float(hi1));
                int off = hoff(b, u0 + ul0);
                __nv_bfloat162 vh; vh.x = hi0; vh.y = hi1;
                __nv_bfloat162 vl; vl.x = lo0; vl.y = lo1;
                *reinterpret_cast<__nv_bfloat162*>(&hsp[off]) = vh;
                *reinterpret_cast<__nv_bfloat162*>(&hsp[off + 8192]) = vl;
            }
        }

        // ---- warp-granular arrival (no __syncthreads in the loop) ----
        __syncwarp();
        if (lane == 0) {
            FENCE_GPU();
            atomicAdd(wbar, 1u);
        }
    }
}

// ---------------- weight split prep ----------------
__global__ void prep_kernel(const float* __restrict__ w) {
    int i = blockIdx.x * blockDim.x + threadIdx.x;
    if (i < 3 * DM * DM) {
        float v = w[i];
        __nv_bfloat16 hi = __float2bfloat16(v);
        g_whi[i] = hi;
        g_wlo[i] = __float2bfloat16(v - __bfloat162float(hi));
    }
}

// out_w fp16 split prep (rows padded to 64 with zeros)
__global__ void prep_ow_kernel(const float* __restrict__ ow) {
    int i = blockIdx.x * blockDim.x + threadIdx.x;
    if (i < 64 * DM) {
        int r = i >> 9;
        float v = (r < ENC) ? ow[(size_t)r * DM + (i & 511)] : 0.f;
        __half hi = __float2half_rn(v);
        g_owhi[i] = hi;
        g_owlo[i] = __float2half_rn(v - __half2float(hi));
    }
}

// ---------------- h0 ----------------
__global__ void h0_kernel(const float* __restrict__ z,
                          const float* __restrict__ w,
                          const float* __restrict__ bias) {
    __shared__ float zs[LATENT];
    const int b = blockIdx.x;
    const int j = threadIdx.x;
    if (b == 0 && j < 4) g_wbar[j << 5] = 0;   // reset per replay
    if (threadIdx.x < LATENT) zs[threadIdx.x] = z[b * LATENT + threadIdx.x];
    __syncthreads();
    float acc = 0.f;
    const float4* wr = reinterpret_cast<const float4*>(w + (size_t)j * LATENT);
#pragma unroll
    for (int k4 = 0; k4 < LATENT / 4; k4++) {
        float4 w4 = __ldg(&wr[k4]);
        acc += zs[4 * k4 + 0] * w4.x + zs[4 * k4 + 1] * w4.y
             + zs[4 * k4 + 2] * w4.z + zs[4 * k4 + 3] * w4.w;
    }
    float h = tanhf(acc + bias[j]);
    g_hs[(size_t)b * DM + j] = h;
    __nv_bfloat16 hi = __float2bfloat16(h);
    int off = hoff(b, j);
    g_hsp[0][off] = hi;
    g_hsp[0][off + 8192] = __float2bfloat16(h - __bfloat162float(hi));
}

// ---------------- output GEMM: tensor cores, fp16 H x fp16-split W ----------------
#define OH_OFF 0
#define OW_OFF 32768
#define ODYN   65536
__global__ void __launch_bounds__(256)
out_kernel(const float* __restrict__ out_b, float* __restrict__ out) {
    extern __shared__ char odyn[];
    const int R0  = blockIdx.x * 128;
    const int tid = threadIdx.x;
    const int lane = tid & 31;
    const int warp = tid >> 5;
    const int wm = warp >> 1;
    const int wn = warp & 1;
    const uint32_t sb = smem_u32(odyn);
    const __half* __restrict__ hsrc = g_hf16 + (size_t)BS;

    float cf[2][4][4] = {};

    const int arowl = (lane & 7) + ((lane >> 3) & 1) * 8;
    const int aHalf = (lane >> 4) & 1;
    const int sA = arowl & 7;
    const int wrow = (lane & 7);
    const int sW = wrow;
    const int wHalf = (lane >> 3) & 1;

    for (int kc = 0; kc < 4; kc++) {
#pragma unroll
        for (int p = 0; p < 8; p++) {
            int idx = tid + 256 * p;
            int row = idx >> 4, c = idx & 15;
            cp16(sb + OH_OFF + row * 256 + ((c ^ (row & 7)) << 4),
                 hsrc + (size_t)(R0 + row) * DM + kc * 128 + c * 8);
        }
#pragma unroll
        for (int p = 0; p < 4; p++) {
            int idx = tid + 256 * p;
            int row = idx >> 4, c = idx & 15;
            cp16(sb + OW_OFF + row * 256 + ((c ^ (row & 7)) << 4),
                 g_owhi + (size_t)row * DM + kc * 128 + c * 8);
        }
#pragma unroll
        for (int p = 0; p < 4; p++) {
            int idx = tid + 256 * p;
            int row = idx >> 4, c = idx & 15;
            cp16(sb + OW_OFF + 16384 + row * 256 + ((c ^ (row & 7)) << 4),
                 g_owlo + (size_t)row * DM + kc * 128 + c * 8);
        }
        CP_COMMIT();
        cp_wait<0>();
        __syncthreads();

        const uint32_t aB = sb + OH_OFF + (uint32_t)(wm * 32 + arowl) * 256;
        const uint32_t wB = sb + OW_OFF + (uint32_t)(wn * 32 + wrow) * 256;
#pragma unroll
        for (int kk = 0; kk < 8; kk++) {
            const int cA = kk * 2 + aHalf;
            uint32_t ah0[4], ah1[4];
            ldsm_x4(ah0, aB + (uint32_t)((cA ^ sA) << 4));
            ldsm_x4(ah1, aB + 16 * 256 + (uint32_t)((cA ^ sA) << 4));
            const int cW = kk * 2 + wHalf;
            const uint32_t wOff = (uint32_t)((cW ^ sW) << 4);
            uint32_t bh[4][2], bl[4][2];
#pragma unroll
            for (int nt = 0; nt < 4; nt++) {
                ldsm_x2(bh[nt], wB + nt * 8 * 256 + wOff);
                ldsm_x2(bl[nt], wB + nt * 8 * 256 + 16384 + wOff);
            }
#pragma unroll
            for (int nt = 0; nt < 4; nt++) {
                mma_f16(cf[0][nt], ah0, bh[nt]);
                mma_f16(cf[0][nt], ah0, bl[nt]);
                mma_f16(cf[1][nt], ah1, bh[nt]);
                mma_f16(cf[1][nt], ah1, bl[nt]);
            }
        }
        __syncthreads();
    }

    const int c_lo = (lane & 3) * 2;
    const int r_in = lane >> 2;
#pragma unroll
    for (int mt = 0; mt < 2; mt++) {
#pragma unroll
        for (int nt = 0; nt < 4; nt++) {
            int col = wn * 32 + nt * 8 + c_lo;
            if (col >= ENC) continue;
            float b0 = __ldg(&out_b[col]);
            bool ok1 = (col + 1) < ENC;
            float b1 = ok1 ? __ldg(&out_b[col + 1]) : 0.f;
#pragma unroll
            for (int hh = 0; hh < 2; hh++) {
                int R = R0 + wm * 32 + mt * 16 + r_in + hh * 8;
                int tt = R >> 8, b = R & 255;
                float* o = &out[((size_t)b * WIN + tt) * ENC + col];
                o[0] = cf[mt][nt][hh * 2 + 0] + b0;
                if (ok1) o[1] = cf[mt][nt][hh * 2 + 1] + b1;
            }
        }
    }
}

// ---------------- launch ----------------
extern "C" void kernel_launch(void* const* d_in, const int* in_sizes, int n_in,
                              void* d_out, int out_size) {
    (void)in_sizes; (void)n_in; (void)out_size;
    const float* z        = (const float*)d_in[0];
    const float* h_proj_w = (const float*)d_in[1];
    const float* h_proj_b = (const float*)d_in[2];
    const float* w_hh     = (const float*)d_in[4];
    const float* b_ih     = (const float*)d_in[5];
    const float* b_hh     = (const float*)d_in[6];
    const float* out_w    = (const float*)d_in[7];
    const float* out_b    = (const float*)d_in[8];
    float* out = (float*)d_out;

    static bool attr_done = false;
    if (!attr_done) {
        cudaFuncSetAttribute(gru_persistent,
                             cudaFuncAttributeMaxDynamicSharedMemorySize, DYN_BYTES);
        cudaFuncSetAttribute(out_kernel,
                             cudaFuncAttributeMaxDynamicSharedMemorySize, ODYN);
        attr_done = true;
    }

    prep_kernel<<<(3 * DM * DM + 255) / 256, 256>>>(w_hh);
    prep_ow_kernel<<<(64 * DM + 255) / 256, 256>>>(out_w);
    h0_kernel<<<BATCH, DM>>>(z, h_proj_w, h_proj_b);
    gru_persistent<<<NCTA, 256, DYN_BYTES>>>(b_ih, b_hh);
    out_kernel<<<(WIN * BATCH) / 128, 256, ODYN>>>(out_b, out);
}